// round 2
// baseline (speedup 1.0000x reference)
#include <cuda_runtime.h>
#include <cuda_bf16.h>

// Problem constants (shapes fixed by the benchmark)
#define B_DIM 4
#define L_DIM 4096
#define D_DIM 2048
#define G_DIM 8
#define NUM_COEF 6
#define DEN_COEF 4   // b1..b4 ; denominator degree-0 coeff is 1 (after abs)

#define N_ELEM    (B_DIM * L_DIM * D_DIM)      // 33,554,432
#define N_CHUNK   (N_ELEM / 4)                 // 8,388,608 float4 chunks
#define D_CHUNK   (D_DIM / 4)                  // 512 float4 per (b,l) row
#define DPG_CHUNK (D_DIM / G_DIM / 4)          // 64 float4 per group

__global__ __launch_bounds__(256, 8)
void rational_group_kernel(const float4* __restrict__ x,
                           const float*  __restrict__ wnum,   // (1,6) broadcast
                           const float*  __restrict__ wden,   // (8,4)
                           float4* __restrict__ out)
{
    unsigned int c = blockIdx.x * blockDim.x + threadIdx.x;
    if (c >= (unsigned int)N_CHUNK) return;

    // Group of this float4 chunk (all 4 elems share it: Dpg=256 is 4-aligned)
    unsigned int g = (c & (D_CHUNK - 1)) / DPG_CHUNK;

    // Warp-uniform coefficient loads: broadcast in L1, negligible cost.
    float a0 = __ldg(&wnum[0]);
    float a1 = __ldg(&wnum[1]);
    float a2 = __ldg(&wnum[2]);
    float a3 = __ldg(&wnum[3]);
    float a4 = __ldg(&wnum[4]);
    float a5 = __ldg(&wnum[5]);

    const float* wd = wden + g * DEN_COEF;
    float c1 = fabsf(__ldg(&wd[0]));
    float c2 = fabsf(__ldg(&wd[1]));
    float c3 = fabsf(__ldg(&wd[2]));
    float c4 = fabsf(__ldg(&wd[3]));

    float4 v = x[c];
    float4 r;

    {
        float z = v.x;
        float num = fmaf(fmaf(fmaf(fmaf(fmaf(a5, z, a4), z, a3), z, a2), z, a1), z, a0);
        float den = fmaf(fmaf(fmaf(fmaf(c4, z, c3), z, c2), z, c1), z, 1.0f);
        r.x = num / den;
    }
    {
        float z = v.y;
        float num = fmaf(fmaf(fmaf(fmaf(fmaf(a5, z, a4), z, a3), z, a2), z, a1), z, a0);
        float den = fmaf(fmaf(fmaf(fmaf(c4, z, c3), z, c2), z, c1), z, 1.0f);
        r.y = num / den;
    }
    {
        float z = v.z;
        float num = fmaf(fmaf(fmaf(fmaf(fmaf(a5, z, a4), z, a3), z, a2), z, a1), z, a0);
        float den = fmaf(fmaf(fmaf(fmaf(c4, z, c3), z, c2), z, c1), z, 1.0f);
        r.z = num / den;
    }
    {
        float z = v.w;
        float num = fmaf(fmaf(fmaf(fmaf(fmaf(a5, z, a4), z, a3), z, a2), z, a1), z, a0);
        float den = fmaf(fmaf(fmaf(fmaf(c4, z, c3), z, c2), z, c1), z, 1.0f);
        r.w = num / den;
    }

    out[c] = r;
}

extern "C" void kernel_launch(void* const* d_in, const int* in_sizes, int n_in,
                              void* d_out, int out_size) {
    const float4* x    = (const float4*)d_in[0];
    const float*  wnum = (const float*)d_in[1];
    const float*  wden = (const float*)d_in[2];
    float4* out        = (float4*)d_out;

    const int threads = 256;
    const int blocks = N_CHUNK / threads;  // 32768, exact cover
    rational_group_kernel<<<blocks, threads>>>(x, wnum, wden, out);
}

// round 3
// speedup vs baseline: 1.0802x; 1.0802x over previous
#include <cuda_runtime.h>
#include <cuda_bf16.h>

// Problem constants (shapes fixed by the benchmark)
#define B_DIM 4
#define L_DIM 4096
#define D_DIM 2048
#define G_DIM 8
#define NUM_COEF 6
#define DEN_COEF 4

#define N_ELEM    (B_DIM * L_DIM * D_DIM)      // 33,554,432
#define N_CHUNK   (N_ELEM / 4)                 // 8,388,608 float4 chunks
#define D_CHUNK   (D_DIM / 4)                  // 512 float4 per (b,l) row
#define DPG_CHUNK (D_DIM / G_DIM / 4)          // 64 float4 per group

#define THREADS 256
#define ITER    4
#define CHUNKS_PER_BLOCK (THREADS * ITER)      // 1024
#define NBLOCKS (N_CHUNK / CHUNKS_PER_BLOCK)   // 8192

__global__ __launch_bounds__(THREADS, 8)
void rational_group_kernel(const float4* __restrict__ x,
                           const float*  __restrict__ wnum,   // (1,6)
                           const float*  __restrict__ wden,   // (8,4)
                           float4* __restrict__ out)
{
    __shared__ float s_a[NUM_COEF];
    __shared__ float s_c[G_DIM * DEN_COEF];

    const unsigned int tid  = threadIdx.x;
    const unsigned int base = blockIdx.x * CHUNKS_PER_BLOCK;

    // Batch all 4 global loads up front -> MLP=4 per thread.
    unsigned int c0 = base + tid;
    unsigned int c1 = c0 + THREADS;
    unsigned int c2 = c1 + THREADS;
    unsigned int c3 = c2 + THREADS;

    float4 v0 = x[c0];
    float4 v1 = x[c1];
    float4 v2 = x[c2];
    float4 v3 = x[c3];

    if (tid < NUM_COEF)            s_a[tid] = wnum[tid];
    if (tid < G_DIM * DEN_COEF)    s_c[tid] = fabsf(wden[tid]);
    __syncthreads();

    const float a0 = s_a[0], a1 = s_a[1], a2 = s_a[2],
                a3 = s_a[3], a4 = s_a[4], a5 = s_a[5];

    unsigned int cs[ITER] = {c0, c1, c2, c3};
    float4       vs[ITER] = {v0, v1, v2, v3};
    float4       rs[ITER];

#pragma unroll
    for (int i = 0; i < ITER; i++) {
        unsigned int g = ((cs[i] & (D_CHUNK - 1)) / DPG_CHUNK) * DEN_COEF;
        float b1 = s_c[g + 0], b2 = s_c[g + 1], b3 = s_c[g + 2], b4 = s_c[g + 3];

        float zx = vs[i].x, zy = vs[i].y, zz = vs[i].z, zw = vs[i].w;

        float nx = fmaf(fmaf(fmaf(fmaf(fmaf(a5, zx, a4), zx, a3), zx, a2), zx, a1), zx, a0);
        float ny = fmaf(fmaf(fmaf(fmaf(fmaf(a5, zy, a4), zy, a3), zy, a2), zy, a1), zy, a0);
        float nz = fmaf(fmaf(fmaf(fmaf(fmaf(a5, zz, a4), zz, a3), zz, a2), zz, a1), zz, a0);
        float nw = fmaf(fmaf(fmaf(fmaf(fmaf(a5, zw, a4), zw, a3), zw, a2), zw, a1), zw, a0);

        float dx = fmaf(fmaf(fmaf(fmaf(b4, zx, b3), zx, b2), zx, b1), zx, 1.0f);
        float dy = fmaf(fmaf(fmaf(fmaf(b4, zy, b3), zy, b2), zy, b1), zy, 1.0f);
        float dz = fmaf(fmaf(fmaf(fmaf(b4, zz, b3), zz, b2), zz, b1), zz, 1.0f);
        float dw = fmaf(fmaf(fmaf(fmaf(b4, zw, b3), zw, b2), zw, b1), zw, 1.0f);

        rs[i].x = __fdividef(nx, dx);
        rs[i].y = __fdividef(ny, dy);
        rs[i].z = __fdividef(nz, dz);
        rs[i].w = __fdividef(nw, dw);
    }

#pragma unroll
    for (int i = 0; i < ITER; i++) {
        out[cs[i]] = rs[i];
    }
}

extern "C" void kernel_launch(void* const* d_in, const int* in_sizes, int n_in,
                              void* d_out, int out_size) {
    const float4* x    = (const float4*)d_in[0];
    const float*  wnum = (const float*)d_in[1];
    const float*  wden = (const float*)d_in[2];
    float4* out        = (float4*)d_out;

    rational_group_kernel<<<NBLOCKS, THREADS>>>(x, wnum, wden, out);
}

// round 4
// speedup vs baseline: 1.0894x; 1.0085x over previous
#include <cuda_runtime.h>
#include <cuda_bf16.h>

// Problem constants (shapes fixed by the benchmark)
#define B_DIM 4
#define L_DIM 4096
#define D_DIM 2048
#define G_DIM 8
#define NUM_COEF 6
#define DEN_COEF 4

#define N_ELEM    (B_DIM * L_DIM * D_DIM)      // 33,554,432
#define N_CHUNK   (N_ELEM / 4)                 // 8,388,608 float4 chunks
#define D_CHUNK   (D_DIM / 4)                  // 512 float4 per (b,l) row
#define DPG_CHUNK (D_DIM / G_DIM / 4)          // 64 float4 per group

#define THREADS 256
#define ITER    8
#define CHUNKS_PER_BLOCK (THREADS * ITER)      // 2048
#define NBLOCKS (N_CHUNK / CHUNKS_PER_BLOCK)   // 4096

__global__ __launch_bounds__(THREADS, 4)
void rational_group_kernel(const float4* __restrict__ x,
                           const float*  __restrict__ wnum,   // (1,6)
                           const float*  __restrict__ wden,   // (8,4)
                           float4* __restrict__ out)
{
    __shared__ float s_a[NUM_COEF];
    __shared__ float s_c[G_DIM * DEN_COEF];

    const unsigned int tid  = threadIdx.x;
    const unsigned int base = blockIdx.x * CHUNKS_PER_BLOCK + tid;

    // Front-batch all 8 streaming loads -> MLP=8 per thread.
    unsigned int cs[ITER];
    float4       vs[ITER];
#pragma unroll
    for (int i = 0; i < ITER; i++) {
        cs[i] = base + i * THREADS;
        vs[i] = __ldcs(&x[cs[i]]);   // evict-first: no reuse, don't pollute L2
    }

    if (tid < NUM_COEF)         s_a[tid] = wnum[tid];
    if (tid < G_DIM * DEN_COEF) s_c[tid] = fabsf(wden[tid]);
    __syncthreads();

    const float a0 = s_a[0], a1 = s_a[1], a2 = s_a[2],
                a3 = s_a[3], a4 = s_a[4], a5 = s_a[5];

#pragma unroll
    for (int i = 0; i < ITER; i++) {
        unsigned int g = ((cs[i] & (D_CHUNK - 1)) / DPG_CHUNK) * DEN_COEF;
        float b1 = s_c[g + 0], b2 = s_c[g + 1], b3 = s_c[g + 2], b4 = s_c[g + 3];

        float zx = vs[i].x, zy = vs[i].y, zz = vs[i].z, zw = vs[i].w;

        float nx = fmaf(fmaf(fmaf(fmaf(fmaf(a5, zx, a4), zx, a3), zx, a2), zx, a1), zx, a0);
        float ny = fmaf(fmaf(fmaf(fmaf(fmaf(a5, zy, a4), zy, a3), zy, a2), zy, a1), zy, a0);
        float nz = fmaf(fmaf(fmaf(fmaf(fmaf(a5, zz, a4), zz, a3), zz, a2), zz, a1), zz, a0);
        float nw = fmaf(fmaf(fmaf(fmaf(fmaf(a5, zw, a4), zw, a3), zw, a2), zw, a1), zw, a0);

        float dx = fmaf(fmaf(fmaf(fmaf(b4, zx, b3), zx, b2), zx, b1), zx, 1.0f);
        float dy = fmaf(fmaf(fmaf(fmaf(b4, zy, b3), zy, b2), zy, b1), zy, 1.0f);
        float dz = fmaf(fmaf(fmaf(fmaf(b4, zz, b3), zz, b2), zz, b1), zz, 1.0f);
        float dw = fmaf(fmaf(fmaf(fmaf(b4, zw, b3), zw, b2), zw, b1), zw, 1.0f);

        float4 r;
        r.x = __fdividef(nx, dx);
        r.y = __fdividef(ny, dy);
        r.z = __fdividef(nz, dz);
        r.w = __fdividef(nw, dw);

        __stcs(&out[cs[i]], r);      // streaming store: evict-first
    }
}

extern "C" void kernel_launch(void* const* d_in, const int* in_sizes, int n_in,
                              void* d_out, int out_size) {
    const float4* x    = (const float4*)d_in[0];
    const float*  wnum = (const float*)d_in[1];
    const float*  wden = (const float*)d_in[2];
    float4* out        = (float4*)d_out;

    rational_group_kernel<<<NBLOCKS, THREADS>>>(x, wnum, wden, out);
}